// round 14
// baseline (speedup 1.0000x reference)
#include <cuda_runtime.h>
#include <cuda_bf16.h>

// NeRF deterministic inverse-CDF sampling — two rays/warp, (A,B)-pair form,
// occupancy-restored (launch_bounds minBlocks=7 -> <=36 regs, ~87% occ).
// Lanes 0-15 = ray A, 16-31 = ray B; shuffles width=16. Lane hl owns bins
// and samples 8hl..8hl+7 of its ray.
//  1. warp-cooperative coalesced weight load -> smem transpose -> 8 lane-minor
//     weights (2x LDS.128); transpose buffer overlays the pair array.
//  2. 7 serial adds + width-16 scan; exact sample boundaries jb via identical
//     fmaf on identical values (exact partition of [0,128)); chained-min guard.
//  3. per-bin affine params out_j = A*j + B as float2 with PADDED addressing
//     addr(i)=8*(i+(i>>3)) (72=8*9, 9 coprime 16 -> conflict-free stores).
//  4. owner ids byte-packed: STS.64 init, STS.8 at starts, LDS.64 readback,
//     width-16 inclusive MAX-scan (segment-id fill).
//  5. per-sample: one LDS.64 + one FMA; 2x STG.128 coalesced.

#define WPB 8
#define FULL 0xffffffffu
#define REGION 1280               // 1152 pair bytes (padded) + 128 owner bytes

__global__ __launch_bounds__(WPB * 32, 7)
void nerf_sample_kernel(const float* __restrict__ rays_o,
                        const float* __restrict__ rays_d,
                        const float* __restrict__ weights,
                        float* __restrict__ out,
                        int R)
{
    __shared__ __align__(16) char s_mem[WPB * 2 * REGION];

    const int warp = threadIdx.x >> 5;
    const int lane = threadIdx.x & 31;
    const int half = lane >> 4;          // 0: ray A, 1: ray B
    const int hl   = lane & 15;          // lane within half
    const int rayA = (blockIdx.x * WPB + warp) * 2;
    const int ray  = rayA + half;
    if (rayA >= R) return;

    char* regA = s_mem + (warp * 2 + 0) * REGION;
    char* regB = s_mem + (warp * 2 + 1) * REGION;
    char* reg  = half ? regB : regA;
    char* ownb = reg + 1152;

    // ---- owner-byte init ----
    *reinterpret_cast<int2*>(ownb + 8 * hl) = make_int2(0, 0);

    // ---- near/far cube intersection; 16-lane redundant per ray ----
    const float* o3 = rays_o + 3 * ray;
    const float* d3 = rays_d + 3 * ray;
    float nearv = -1e30f, farv = 1e30f;
#pragma unroll
    for (int a = 0; a < 3; ++a) {
        float oo  = __ldg(o3 + a);
        float dd  = __ldg(d3 + a) + 1e-15f;
        float inv = __fdividef(1.0f, dd);
        float oi  = oo * inv;
        float t0  = -inv - oi;
        float t1  =  inv - oi;
        nearv = fmaxf(nearv, fminf(t0, t1));
        farv  = fminf(farv,  fmaxf(t0, t1));
    }
    nearv = fmaxf(nearv, 0.05f);
    const float sstep = (farv - nearv) * (1.0f / 127.0f);

    // ---- warp-cooperative coalesced weight load (both rays) ----
    {
        float* wbufA = reinterpret_cast<float*>(regA);
        float* wbufB = reinterpret_cast<float*>(regB);
        const float* wrA = weights + (long long)rayA * 127;
        const float* wrB = wrA + 127;
#pragma unroll
        for (int k = 0; k < 3; ++k) {
            wbufA[lane + 32 * k] = __ldg(wrA + lane + 32 * k) + 1e-5f;
            wbufB[lane + 32 * k] = __ldg(wrB + lane + 32 * k) + 1e-5f;
        }
        wbufA[lane + 96] = (lane < 31) ? (__ldg(wrA + lane + 96) + 1e-5f) : 0.0f;
        wbufB[lane + 96] = (lane < 31) ? (__ldg(wrB + lane + 96) + 1e-5f) : 0.0f;
    }
    __syncwarp();

    // ---- 8 lane-minor weights ----
    const float* myw = reinterpret_cast<const float*>(reg) + 8 * hl;
    float4 wa = *reinterpret_cast<const float4*>(myw);
    float4 wb = *reinterpret_cast<const float4*>(myw + 4);
    __syncwarp();   // transpose buffer dead; pair array may overwrite it

    // ---- local prefix + width-16 scan ----
    const float s1 = wa.x;
    const float s2 = s1 + wa.y;
    const float s3 = s2 + wa.z;
    const float s4 = s3 + wa.w;
    const float s5 = s4 + wb.x;
    const float s6 = s5 + wb.y;
    const float s7 = s6 + wb.z;
    const float s8 = s7 + wb.w;

    float incl = s8;
#pragma unroll
    for (int d = 1; d < 16; d <<= 1) {
        float y = __shfl_up_sync(FULL, incl, d, 16);
        if (hl >= d) incl += y;
    }
    float P = __shfl_up_sync(FULL, incl, 1, 16);
    if (hl == 0) P = 0.0f;
    const float total = __shfl_sync(FULL, incl, 15, 16);
    const float rtot  = __fdividef(1.0f, total);
    const float g     = rtot * 128.0f;     // identical within each half

    const float m1 = P + s1, m2 = P + s2, m3 = P + s3, m4 = P + s4;
    const float m5 = P + s5, m6 = P + s6, m7 = P + s7;

    // ---- per-bin affine params first (keeps b-temps short-lived) ----
    {
        const float sA = sstep * 0.0078125f;   // sstep/128
        const float fi = (float)(8 * hl);
        char* pbase = reg + 72 * hl;           // addr(i)=8*(i+(i>>3))
#define MKPAIR(K, BLO, BHI)  do {                                            \
            float den  = (BHI) - (BLO);                                      \
            float rden = (den < 1e-5f) ? 1.0f : __fdividef(1.0f, den);       \
            float A = sA * rden;                                             \
            float B = fmaf(sstep, (fi + (float)(K)) +                        \
                           (0.00390625f - (BLO)) * rden, nearv);             \
            *reinterpret_cast<float2*>(pbase + 8 * (K)) = make_float2(A, B); \
        } while (0)
        const float b0 = P  * rtot, b1 = m1 * rtot, b2 = m2 * rtot, b3 = m3 * rtot;
        const float b4 = m4 * rtot, b5 = m5 * rtot, b6 = m6 * rtot, b7 = m7 * rtot;
        const float b8 = incl * rtot;
        MKPAIR(0, b0, b1);  MKPAIR(1, b1, b2);  MKPAIR(2, b2, b3);  MKPAIR(3, b3, b4);
        MKPAIR(4, b4, b5);  MKPAIR(5, b5, b6);  MKPAIR(6, b6, b7);  MKPAIR(7, b7, b8);
#undef MKPAIR
    }

    // ---- sample-index boundaries; jb8(hl) == jb0(hl+1) exactly ----
    int jb0 = __float2int_ru(fmaf(P,    g, -0.5f));
    int jb1 = __float2int_ru(fmaf(m1,   g, -0.5f));
    int jb2 = __float2int_ru(fmaf(m2,   g, -0.5f));
    int jb3 = __float2int_ru(fmaf(m3,   g, -0.5f));
    int jb4 = __float2int_ru(fmaf(m4,   g, -0.5f));
    int jb5 = __float2int_ru(fmaf(m5,   g, -0.5f));
    int jb6 = __float2int_ru(fmaf(m6,   g, -0.5f));
    int jb7 = __float2int_ru(fmaf(m7,   g, -0.5f));
    int jb8 = __float2int_ru(fmaf(incl, g, -0.5f));
    jb7 = min(jb7, jb8);  jb6 = min(jb6, jb7);  jb5 = min(jb5, jb6);
    jb4 = min(jb4, jb5);  jb3 = min(jb3, jb4);  jb2 = min(jb2, jb3);
    jb1 = min(jb1, jb2);

    // ---- scatter bin id (byte) at each nonempty bin's start ----
    {
        const int b = 8 * hl;
        if (jb0 < jb1) ownb[jb0] = (char)(b);
        if (jb1 < jb2) ownb[jb1] = (char)(b + 1);
        if (jb2 < jb3) ownb[jb2] = (char)(b + 2);
        if (jb3 < jb4) ownb[jb3] = (char)(b + 3);
        if (jb4 < jb5) ownb[jb4] = (char)(b + 4);
        if (jb5 < jb6) ownb[jb5] = (char)(b + 5);
        if (jb6 < jb7) ownb[jb6] = (char)(b + 6);
        if (jb7 < jb8) ownb[jb7] = (char)(b + 7);
    }
    __syncwarp();

    // ---- owner recovery: byte extract + width-16 inclusive MAX-scan ----
    int2 ow = *reinterpret_cast<const int2*>(ownb + 8 * hl);
    int q0 = ow.x & 0xff;
    int q1 = max(q0, (ow.x >> 8)  & 0xff);
    int q2 = max(q1, (ow.x >> 16) & 0xff);
    int q3 = max(q2, (ow.x >> 24) & 0xff);
    int q4 = max(q3,  ow.y        & 0xff);
    int q5 = max(q4, (ow.y >> 8)  & 0xff);
    int q6 = max(q5, (ow.y >> 16) & 0xff);
    int q7 = max(q6, (ow.y >> 24) & 0xff);

    int v = q7;
#pragma unroll
    for (int d = 1; d < 16; d <<= 1) {
        int y = __shfl_up_sync(FULL, v, d, 16);
        if (hl >= d) v = max(v, y);
    }
    int ex = __shfl_up_sync(FULL, v, 1, 16);
    if (hl == 0) ex = 0;
    const int i0 = max(ex, q0), i1 = max(ex, q1), i2 = max(ex, q2), i3 = max(ex, q3);
    const int i4 = max(ex, q4), i5 = max(ex, q5), i6 = max(ex, q6), i7 = max(ex, q7);

    // ---- gather (A,B), one fma per sample, 2x STG.128 ----
    const int jbase = 8 * hl;
    float* orow = out + (long long)ray * 128 + jbase;

    float4 r1, r2;
#define SAMP(DST, I, K)  do {                                                \
        float2 ab = *reinterpret_cast<const float2*>(                        \
            reg + 8 * ((I) + ((I) >> 3)));                                   \
        DST = fmaf(ab.x, (float)(jbase + (K)), ab.y);                        \
    } while (0)
    SAMP(r1.x, i0, 0);  SAMP(r1.y, i1, 1);  SAMP(r1.z, i2, 2);  SAMP(r1.w, i3, 3);
    SAMP(r2.x, i4, 4);  SAMP(r2.y, i5, 5);  SAMP(r2.z, i6, 6);  SAMP(r2.w, i7, 7);
#undef SAMP
    *reinterpret_cast<float4*>(orow)     = r1;
    *reinterpret_cast<float4*>(orow + 4) = r2;
}

extern "C" void kernel_launch(void* const* d_in, const int* in_sizes, int n_in,
                              void* d_out, int out_size) {
    const float* rays_o  = (const float*)d_in[0];
    const float* rays_d  = (const float*)d_in[1];
    const float* weights = (const float*)d_in[2];
    float* out = (float*)d_out;

    const int R = in_sizes[0] / 3;   // 262144
    const int pairs = (R + 1) / 2;
    dim3 block(WPB * 32);
    dim3 grid((pairs + WPB - 1) / WPB);
    nerf_sample_kernel<<<grid, block>>>(rays_o, rays_d, weights, out, R);
}

// round 15
// speedup vs baseline: 1.1139x; 1.1139x over previous
#include <cuda_runtime.h>
#include <cuda_bf16.h>

// NeRF deterministic inverse-CDF sampling — two rays/warp, (A,B)-pair form,
// register-slimmed (sequential jb/scatter + sequential pair emission),
// launch_bounds(256, 6): no forced spills, 75% occ ceiling.
// Lanes 0-15 = ray A, 16-31 = ray B; shuffles width=16. Lane hl owns bins
// and samples 8hl..8hl+7 of its ray.
//  1. warp-cooperative coalesced weight load -> smem transpose -> 8 lane-minor
//     weights (2x LDS.128); transpose buffer overlays the pair array.
//  2. 7 serial adds + width-16 scan; exact sample boundaries jb via identical
//     fmaf on identical values (exact partition of [0,128)); top-down
//     chained-min fused with the owner-byte scatter (2 live jb regs).
//  3. per-bin affine params out_j = A*j + B as float2, PADDED addressing
//     addr(i)=8*(i+(i>>3)) (72=8*9, 9 coprime 16 -> conflict-free stores),
//     emitted sequentially (2 live b regs).
//  4. owner ids byte-packed in smem; width-16 inclusive MAX-scan fill.
//  5. per-sample: one LDS.64 + one FMA; 2x STG.128 coalesced.

#define WPB 8
#define FULL 0xffffffffu
#define REGION 1280               // 1152 pair bytes (padded) + 128 owner bytes

__global__ __launch_bounds__(WPB * 32, 6)
void nerf_sample_kernel(const float* __restrict__ rays_o,
                        const float* __restrict__ rays_d,
                        const float* __restrict__ weights,
                        float* __restrict__ out,
                        int R)
{
    __shared__ __align__(16) char s_mem[WPB * 2 * REGION];

    const int warp = threadIdx.x >> 5;
    const int lane = threadIdx.x & 31;
    const int half = lane >> 4;          // 0: ray A, 1: ray B
    const int hl   = lane & 15;          // lane within half
    const int rayA = (blockIdx.x * WPB + warp) * 2;
    const int ray  = rayA + half;
    if (rayA >= R) return;

    char* regA = s_mem + (warp * 2 + 0) * REGION;
    char* regB = s_mem + (warp * 2 + 1) * REGION;
    char* reg  = half ? regB : regA;
    char* ownb = reg + 1152;

    // ---- owner-byte init ----
    *reinterpret_cast<int2*>(ownb + 8 * hl) = make_int2(0, 0);

    // ---- near/far cube intersection; 16-lane redundant per ray ----
    const float* o3 = rays_o + 3 * ray;
    const float* d3 = rays_d + 3 * ray;
    float nearv = -1e30f, farv = 1e30f;
#pragma unroll
    for (int a = 0; a < 3; ++a) {
        float oo  = __ldg(o3 + a);
        float dd  = __ldg(d3 + a) + 1e-15f;
        float inv = __fdividef(1.0f, dd);
        float oi  = oo * inv;
        float t0  = -inv - oi;
        float t1  =  inv - oi;
        nearv = fmaxf(nearv, fminf(t0, t1));
        farv  = fminf(farv,  fmaxf(t0, t1));
    }
    nearv = fmaxf(nearv, 0.05f);
    const float sstep = (farv - nearv) * (1.0f / 127.0f);

    // ---- warp-cooperative coalesced weight load (both rays) ----
    {
        float* wbufA = reinterpret_cast<float*>(regA);
        float* wbufB = reinterpret_cast<float*>(regB);
        const float* wrA = weights + (long long)rayA * 127;
        const float* wrB = wrA + 127;
#pragma unroll
        for (int k = 0; k < 3; ++k) {
            wbufA[lane + 32 * k] = __ldg(wrA + lane + 32 * k) + 1e-5f;
            wbufB[lane + 32 * k] = __ldg(wrB + lane + 32 * k) + 1e-5f;
        }
        wbufA[lane + 96] = (lane < 31) ? (__ldg(wrA + lane + 96) + 1e-5f) : 0.0f;
        wbufB[lane + 96] = (lane < 31) ? (__ldg(wrB + lane + 96) + 1e-5f) : 0.0f;
    }
    __syncwarp();

    // ---- 8 lane-minor weights ----
    const float* myw = reinterpret_cast<const float*>(reg) + 8 * hl;
    float4 wa = *reinterpret_cast<const float4*>(myw);
    float4 wb = *reinterpret_cast<const float4*>(myw + 4);
    __syncwarp();   // transpose buffer dead; pair array may overwrite it

    // ---- local prefix + width-16 scan ----
    const float s1 = wa.x;
    const float s2 = s1 + wa.y;
    const float s3 = s2 + wa.z;
    const float s4 = s3 + wa.w;
    const float s5 = s4 + wb.x;
    const float s6 = s5 + wb.y;
    const float s7 = s6 + wb.z;
    const float s8 = s7 + wb.w;

    float incl = s8;
#pragma unroll
    for (int d = 1; d < 16; d <<= 1) {
        float y = __shfl_up_sync(FULL, incl, d, 16);
        if (hl >= d) incl += y;
    }
    float P = __shfl_up_sync(FULL, incl, 1, 16);
    if (hl == 0) P = 0.0f;
    const float total = __shfl_sync(FULL, incl, 15, 16);
    const float rtot  = __fdividef(1.0f, total);
    const float g     = rtot * 128.0f;     // identical within each half

    const float m1 = P + s1, m2 = P + s2, m3 = P + s3, m4 = P + s4;
    const float m5 = P + s5, m6 = P + s6, m7 = P + s7;

    // ---- top-down jb computation fused with owner-byte scatter ----
    // jb8(hl) == jb0(hl+1) exactly (identical fmaf on identical values).
    {
        const int b = 8 * hl;
        int jnext = __float2int_ru(fmaf(incl, g, -0.5f));   // jb8
        int j;
#define STEP(MK, K)  do {                                                    \
            j = min(__float2int_ru(fmaf((MK), g, -0.5f)), jnext);            \
            if (j < jnext) ownb[j] = (char)(b + (K));                        \
            jnext = j;                                                       \
        } while (0)
        STEP(m7, 7); STEP(m6, 6); STEP(m5, 5); STEP(m4, 4);
        STEP(m3, 3); STEP(m2, 2); STEP(m1, 1); STEP(P,  0);
#undef STEP
    }

    // ---- per-bin affine params, sequential (2 live b regs) ----
    {
        const float sA = sstep * 0.0078125f;   // sstep/128
        const float fi = (float)(8 * hl);
        char* pbase = reg + 72 * hl;           // addr(i)=8*(i+(i>>3))
        float blo = P * rtot;
#define MKPAIR(K, MHI)  do {                                                 \
            float bhi  = (MHI) * rtot;                                       \
            float den  = bhi - blo;                                          \
            float rden = (den < 1e-5f) ? 1.0f : __fdividef(1.0f, den);       \
            float A = sA * rden;                                             \
            float B = fmaf(sstep, (fi + (float)(K)) +                        \
                           (0.00390625f - blo) * rden, nearv);               \
            *reinterpret_cast<float2*>(pbase + 8 * (K)) = make_float2(A, B); \
            blo = bhi;                                                       \
        } while (0)
        MKPAIR(0, m1);  MKPAIR(1, m2);  MKPAIR(2, m3);  MKPAIR(3, m4);
        MKPAIR(4, m5);  MKPAIR(5, m6);  MKPAIR(6, m7);  MKPAIR(7, incl);
#undef MKPAIR
    }
    __syncwarp();

    // ---- owner recovery: byte extract + width-16 inclusive MAX-scan ----
    int2 ow = *reinterpret_cast<const int2*>(ownb + 8 * hl);
    int q0 = ow.x & 0xff;
    int q1 = max(q0, (ow.x >> 8)  & 0xff);
    int q2 = max(q1, (ow.x >> 16) & 0xff);
    int q3 = max(q2, (ow.x >> 24) & 0xff);
    int q4 = max(q3,  ow.y        & 0xff);
    int q5 = max(q4, (ow.y >> 8)  & 0xff);
    int q6 = max(q5, (ow.y >> 16) & 0xff);
    int q7 = max(q6, (ow.y >> 24) & 0xff);

    int v = q7;
#pragma unroll
    for (int d = 1; d < 16; d <<= 1) {
        int y = __shfl_up_sync(FULL, v, d, 16);
        if (hl >= d) v = max(v, y);
    }
    int ex = __shfl_up_sync(FULL, v, 1, 16);
    if (hl == 0) ex = 0;
    const int i0 = max(ex, q0), i1 = max(ex, q1), i2 = max(ex, q2), i3 = max(ex, q3);
    const int i4 = max(ex, q4), i5 = max(ex, q5), i6 = max(ex, q6), i7 = max(ex, q7);

    // ---- gather (A,B), one fma per sample, 2x STG.128 ----
    const int jbase = 8 * hl;
    float* orow = out + (long long)ray * 128 + jbase;

    float4 r1, r2;
#define SAMP(DST, I, K)  do {                                                \
        float2 ab = *reinterpret_cast<const float2*>(                        \
            reg + 8 * ((I) + ((I) >> 3)));                                   \
        DST = fmaf(ab.x, (float)(jbase + (K)), ab.y);                        \
    } while (0)
    SAMP(r1.x, i0, 0);  SAMP(r1.y, i1, 1);  SAMP(r1.z, i2, 2);  SAMP(r1.w, i3, 3);
    SAMP(r2.x, i4, 4);  SAMP(r2.y, i5, 5);  SAMP(r2.z, i6, 6);  SAMP(r2.w, i7, 7);
#undef SAMP
    *reinterpret_cast<float4*>(orow)     = r1;
    *reinterpret_cast<float4*>(orow + 4) = r2;
}

extern "C" void kernel_launch(void* const* d_in, const int* in_sizes, int n_in,
                              void* d_out, int out_size) {
    const float* rays_o  = (const float*)d_in[0];
    const float* rays_d  = (const float*)d_in[1];
    const float* weights = (const float*)d_in[2];
    float* out = (float*)d_out;

    const int R = in_sizes[0] / 3;   // 262144
    const int pairs = (R + 1) / 2;
    dim3 block(WPB * 32);
    dim3 grid((pairs + WPB - 1) / WPB);
    nerf_sample_kernel<<<grid, block>>>(rays_o, rays_d, weights, out, R);
}